// round 16
// baseline (speedup 1.0000x reference)
#include <cuda_runtime.h>
#include <cuda_fp16.h>
#include <math.h>
#include <stdint.h>

// Problem constants
#define NN    6144
#define DD    128
#define NCLS  20
#define NB    5

#define ITILES 48                     // 6144/128
#define NPAIRS (ITILES*(ITILES+1)/2)  // 1176 tile pairs (I<=J)
#define NORMB 384                     // k_prep blocks

// SMEM layout for k_main. Tile rows = 256B (128 fp16), 16B-chunk XOR swizzle.
#define OFF_A    0
#define OFF_B    32768
#define OFF_KI   65536
#define OFF_KJ   (OFF_KI + 512)
#define SMEM_TOTAL (OFF_KJ + 512)    // ~65.5KB -> 2 CTA/SM

__device__ __forceinline__ uint32_t smem_u32(const void* p) {
    uint32_t a;
    asm("{ .reg .u64 t; cvta.to.shared.u64 t, %1; cvt.u32.u64 %0, t; }" : "=r"(a) : "l"(p));
    return a;
}

#define LDSM_X4(r0, r1, r2, r3, addr) \
    asm volatile("ldmatrix.sync.aligned.m8n8.x4.shared.b16 {%0,%1,%2,%3}, [%4];" \
                 : "=r"(r0), "=r"(r1), "=r"(r2), "=r"(r3) : "r"(addr))

#define MMA_F16(c, a, b0, b1) \
    asm volatile("mma.sync.aligned.m16n8k16.row.col.f32.f16.f16.f32 " \
                 "{%0,%1,%2,%3}, {%4,%5,%6,%7}, {%8,%9}, {%0,%1,%2,%3};" \
                 : "+f"((c)[0]), "+f"((c)[1]), "+f"((c)[2]), "+f"((c)[3]) \
                 : "r"((a)[0]), "r"((a)[1]), "r"((a)[2]), "r"((a)[3]), "r"(b0), "r"(b1))

// ---------------- Scratch (device globals; zero-initialized at load) -------
__device__ __half g_h[NN * DD];
__device__ float g_sum[NN * 4];             // per-row (pt, nt, pb, nb); zeroed by k_prep
__device__ int   g_hist_t[NCLS];            // zeroed at load; re-zeroed by k_fin
__device__ int   g_hist_tb[NCLS * NB];
__device__ float g_cls[32];                 // class loss sums; re-zeroed by k_fin

// ---------------------------------------------------------------------------
// Kernel 1: normalize+fp16; histogram own 16 rows (global int atomics);
// zero this call's slice of g_sum (runs before k_main in-stream).
// ---------------------------------------------------------------------------
__global__ void k_prep(const float* __restrict__ x,
                       const int* __restrict__ targets,
                       const int* __restrict__ batch0) {
    int tid  = threadIdx.x;
    int row0 = blockIdx.x * 16 + (tid >> 5) * 2;
    int lane = tid & 31;
    float4 v0 = *(const float4*)(x + (size_t)row0 * DD + lane * 4);
    float4 v1 = *(const float4*)(x + (size_t)(row0 + 1) * DD + lane * 4);
    float s0 = v0.x * v0.x + v0.y * v0.y + v0.z * v0.z + v0.w * v0.w;
    float s1 = v1.x * v1.x + v1.y * v1.y + v1.z * v1.z + v1.w * v1.w;
    #pragma unroll
    for (int o = 16; o; o >>= 1) {
        s0 += __shfl_xor_sync(0xffffffffu, s0, o);
        s1 += __shfl_xor_sync(0xffffffffu, s1, o);
    }
    float i0 = 1.0f / fmaxf(sqrtf(s0), 1e-8f);
    float i1 = 1.0f / fmaxf(sqrtf(s1), 1e-8f);
    size_t b0 = (size_t)row0 * DD + lane * 4;
    *(__half2*)(g_h + b0)          = __floats2half2_rn(v0.x * i0, v0.y * i0);
    *(__half2*)(g_h + b0 + 2)      = __floats2half2_rn(v0.z * i0, v0.w * i0);
    *(__half2*)(g_h + b0 + DD)     = __floats2half2_rn(v1.x * i1, v1.y * i1);
    *(__half2*)(g_h + b0 + DD + 2) = __floats2half2_rn(v1.z * i1, v1.w * i1);

    if (tid < 16) {
        // zero this block's 16 rows of g_sum (float4 each)
        *(float4*)(g_sum + (size_t)(blockIdx.x * 16 + tid) * 4) =
            make_float4(0.f, 0.f, 0.f, 0.f);
        // histogram
        int r = blockIdx.x * 16 + tid;
        int t = targets[r], b = batch0[r];
        atomicAdd(&g_hist_t[t], 1);
        atomicAdd(&g_hist_tb[t * NB + b], 1);
    }
}

// ---------------------------------------------------------------------------
// Templated epilogue (DIAG: self-exclusion; FAST: t==0.25 -> et = eb*eb).
// Results go straight to g_sum via float atomics (RED.ADD).
// ---------------------------------------------------------------------------
template <bool DIAG, bool FAST>
__device__ __forceinline__ void epilogue(
    const float (&acc)[4][4][4],
    const uint32_t (&kIa)[2], const uint32_t* kj8,
    float inv_t, int Ibase, int Jbase,
    int wm, int wn, int g, int q)
{
    float all2[8], st2[8], sb2[8], pb2[8];
    #pragma unroll
    for (int k = 0; k < 8; k++) { all2[k]=st2[k]=sb2[k]=pb2[k]=0.f; }

    #pragma unroll
    for (int mi = 0; mi < 4; mi++) {
        float a1[2] = {0.f, 0.f}, s1[2] = {0.f, 0.f};
        float b1[2] = {0.f, 0.f}, p1[2] = {0.f, 0.f};
        uint32_t kib[2];
        #pragma unroll
        for (int h = 0; h < 2; h++) {
            int pi = mi * 2 + h;
            kib[h] = (kIa[pi >> 2] >> ((pi & 3) * 8)) & 0xFFu;
        }

        #pragma unroll
        for (int ni = 0; ni < 4; ni++) {
            #pragma unroll
            for (int e = 0; e < 4; e++) {
                const int h  = e >> 1, l = e & 1;
                const int pj = ni * 2 + l;
                uint32_t x = kib[h] ^ kj8[pj];
                bool same_t = (x < 8u);
                bool eq     = (x == 0u);
                float s  = acc[mi][ni][e];
                float eb, et;
                if (FAST) { eb = __expf(s + s); et = eb * eb; }
                else      { eb = __expf(s + s); et = __expf(s * inv_t); }
                if (DIAG) {
                    bool self = ((wm * 64 + mi * 16 + h * 8 + g) ==
                                 (wn * 32 + ni * 8 + 2 * q + l));
                    et = self ? 0.f : et;
                    eb = self ? 0.f : eb;
                }
                float et_st = same_t ? et : 0.f;
                float eb_st = same_t ? eb : 0.f;
                float eb_eq = eq     ? eb : 0.f;
                a1[h] += et;    s1[h] += et_st;   b1[h] += eb_st;   p1[h] += eb_eq;
                all2[pj] += et; st2[pj] += et_st; sb2[pj] += eb_st; pb2[pj] += eb_eq;
            }
        }
        // Side-1: reduce over 4 q-lanes, then RED straight to g_sum.
        #pragma unroll
        for (int h = 0; h < 2; h++) {
            float pt = s1[h];
            float nt = a1[h] - s1[h];
            float pb = p1[h];
            float nb = b1[h] - p1[h];
            #pragma unroll
            for (int o = 1; o <= 2; o <<= 1) {
                pt += __shfl_xor_sync(0xffffffffu, pt, o);
                nt += __shfl_xor_sync(0xffffffffu, nt, o);
                pb += __shfl_xor_sync(0xffffffffu, pb, o);
                nb += __shfl_xor_sync(0xffffffffu, nb, o);
            }
            if (q == 0) {
                int row = Ibase + wm * 64 + mi * 16 + h * 8 + g;
                float* dst = g_sum + (size_t)row * 4;
                atomicAdd(dst + 0, pt);
                atomicAdd(dst + 1, nt);
                atomicAdd(dst + 2, pb);
                atomicAdd(dst + 3, nb);
            }
        }
    }

    // Side-2: reduce over 8 g-lanes, RED to g_sum (both wm warps merge via RED).
    if (!DIAG) {
        #pragma unroll
        for (int k = 0; k < 8; k++) {
            float pt = st2[k];
            float nt = all2[k] - st2[k];
            float pb = pb2[k];
            float nb = sb2[k] - pb2[k];
            #pragma unroll
            for (int o = 4; o <= 16; o <<= 1) {
                pt += __shfl_xor_sync(0xffffffffu, pt, o);
                nt += __shfl_xor_sync(0xffffffffu, nt, o);
                pb += __shfl_xor_sync(0xffffffffu, pb, o);
                nb += __shfl_xor_sync(0xffffffffu, nb, o);
            }
            if (g == 0) {
                int row = Jbase + wn * 32 + (k >> 1) * 8 + 2 * q + (k & 1);
                float* dst = g_sum + (size_t)row * 4;
                atomicAdd(dst + 0, pt);
                atomicAdd(dst + 1, nt);
                atomicAdd(dst + 2, pb);
                atomicAdd(dst + 3, nb);
            }
        }
    }
}

// ---------------------------------------------------------------------------
// Kernel 2: one CTA per tile pair (I,J), I<=J.
// ---------------------------------------------------------------------------
__device__ __forceinline__ void fill_tile(char* smem, int off,
                                          const __half* __restrict__ src,
                                          int rowbase, int tid) {
    #pragma unroll
    for (int it = 0; it < 8; it++) {
        int lin = it * 256 + tid;
        int n   = lin >> 4;
        int c16 = lin & 15;
        uint4 v = *(const uint4*)(src + (size_t)(rowbase + n) * DD + c16 * 8);
        *(uint4*)(smem + off + n * 256 + ((c16 ^ (n & 7)) << 4)) = v;
    }
}

__global__ void __launch_bounds__(256, 2)
k_main(const float* __restrict__ d_temp,
       const int*   __restrict__ targets,
       const int*   __restrict__ batch0) {
    extern __shared__ char smem[];
    const uint32_t sb = smem_u32(smem);
    const int tid = threadIdx.x;
    const int L   = tid & 31;
    const int w   = tid >> 5;
    const int wm  = w & 1;
    const int wn  = w >> 1;

    int p = blockIdx.x, I = 0;
    while (p >= ITILES - I) { p -= ITILES - I; I++; }
    const int J = I + p;
    const int Ibase = I * 128;
    const int Jbase = J * 128;
    const bool diag = (I == J);

    int* sm_ki = (int*)(smem + OFF_KI);
    int* sm_kj = (int*)(smem + OFF_KJ);

    const float t     = fminf(fmaxf(d_temp[0], 0.1f), 1.0f);
    const float inv_t = 1.0f / t;
    const bool  fast  = (inv_t == 4.0f);

    fill_tile(smem, OFF_A, g_h, Ibase, tid);
    fill_tile(smem, OFF_B, g_h, Jbase, tid);
    if (tid < 128) {
        sm_ki[tid] = targets[Ibase + tid] * 8 + batch0[Ibase + tid];
    } else {
        int r = tid - 128;
        sm_kj[r] = targets[Jbase + r] * 8 + batch0[Jbase + r];
    }
    __syncthreads();

    const int la15 = L & 15;
    const int l4   = L >> 4;
    const int lb7  = (L & 7) + ((L >> 4) << 3);
    const int lb1  = (L >> 3) & 1;

    float acc[4][4][4];
    #pragma unroll
    for (int mi = 0; mi < 4; mi++)
        #pragma unroll
        for (int ni = 0; ni < 4; ni++)
            #pragma unroll
            for (int e = 0; e < 4; e++) acc[mi][ni][e] = 0.f;

    #pragma unroll
    for (int ks = 0; ks < 8; ks++) {
        uint32_t a[4][4], b[2][4];
        #pragma unroll
        for (int mi = 0; mi < 4; mi++) {
            int rowA = wm * 64 + mi * 16 + la15;
            uint32_t ad = sb + OFF_A + rowA * 256 + (((ks * 2 + l4) ^ (rowA & 7)) << 4);
            LDSM_X4(a[mi][0], a[mi][1], a[mi][2], a[mi][3], ad);
        }
        #pragma unroll
        for (int np = 0; np < 2; np++) {
            int rowB = wn * 32 + np * 16 + lb7;
            uint32_t bd = sb + OFF_B + rowB * 256 + (((ks * 2 + lb1) ^ (rowB & 7)) << 4);
            LDSM_X4(b[np][0], b[np][1], b[np][2], b[np][3], bd);
        }
        #pragma unroll
        for (int mi = 0; mi < 4; mi++)
            #pragma unroll
            for (int ni = 0; ni < 4; ni++)
                MMA_F16(acc[mi][ni], a[mi],
                        b[ni >> 1][(ni & 1) * 2], b[ni >> 1][(ni & 1) * 2 + 1]);
    }

    const int g = L >> 2, q = L & 3;

    uint32_t kIa[2] = {0u, 0u};
    uint32_t kj8[8];
    #pragma unroll
    for (int pk = 0; pk < 8; pk++) {
        int row = wm * 64 + (pk >> 1) * 16 + (pk & 1) * 8 + g;
        kIa[pk >> 2] |= ((uint32_t)sm_ki[row]) << ((pk & 3) * 8);
        int col = wn * 32 + (pk >> 1) * 8 + 2 * q + (pk & 1);
        kj8[pk] = (uint32_t)sm_kj[col];
    }

    if (diag) {
        if (fast) epilogue<true,  true >(acc, kIa, kj8, inv_t, Ibase, Jbase, wm, wn, g, q);
        else      epilogue<true,  false>(acc, kIa, kj8, inv_t, Ibase, Jbase, wm, wn, g, q);
    } else {
        if (fast) epilogue<false, true >(acc, kIa, kj8, inv_t, Ibase, Jbase, wm, wn, g, q);
        else      epilogue<false, false>(acc, kIa, kj8, inv_t, Ibase, Jbase, wm, wn, g, q);
    }
}

// ---------------------------------------------------------------------------
// Kernel 3: tail (24 blocks x 256 thr; one row/thread).  Reads g_sum (98KB),
// computes per-row losses, accumulates class sums via smem + global RED.
// ---------------------------------------------------------------------------
__global__ void k_tail(const int* __restrict__ targets,
                       const int* __restrict__ batch0) {
    __shared__ float cls[32];
    const int tid = threadIdx.x;
    if (tid < 32) cls[tid] = 0.f;
    __syncthreads();

    const int i = blockIdx.x * 256 + tid;
    float4 v = *(const float4*)(g_sum + (size_t)i * 4);
    int tcl = targets[i], bcl = batch0[i];
    int cp  = g_hist_t[tcl];
    bool valid_t = (cp >= 2) && ((NN - cp) >= 1);
    int cpb = g_hist_tb[tcl * NB + bcl];
    int cnb = cp - cpb;
    bool valid_b = (cpb >= 2) && (cnb >= 1);
    float lt = valid_t ? logf((v.x + v.y) / v.x) : 0.0f;
    float lb = valid_b ? (1.0f / logf((v.z + v.w) / v.z)) : 0.0f;

    atomicAdd(&cls[tcl], lt);
    atomicAdd(&cls[NCLS + bcl], lb);
    __syncthreads();

    if (tid < NCLS + NB) atomicAdd(&g_cls[tid], cls[tid]);
}

// ---------------------------------------------------------------------------
// Kernel 4: final scalar (128 threads) + re-zero g_cls & histograms.
// ---------------------------------------------------------------------------
__global__ void k_fin(const float* __restrict__ w_t,
                      const float* __restrict__ w_b,
                      float* __restrict__ out) {
    int tid = threadIdx.x;

    if (tid < 32) {
        float tot = (tid < NCLS + NB) ? g_cls[tid] : 0.f;
        float contrib = 0.f;
        if (tid < NCLS) {
            int cp = g_hist_t[tid];
            bool valid = (cp >= 2) && ((NN - cp) >= 1);
            float cnt = valid ? (float)cp : 0.f;
            float mean = tot / fmaxf(cnt, 1.0f);
            if (cnt > 0.f) contrib = 0.9f * mean * w_t[tid];
        } else if (tid < NCLS + NB) {
            int bc = tid - NCLS;
            float cnt = 0.f;
            for (int tc = 0; tc < NCLS; tc++) {
                int cpb = g_hist_tb[tc * NB + bc];
                int cnb = g_hist_t[tc] - cpb;
                if ((cpb >= 2) && (cnb >= 1)) cnt += (float)cpb;
            }
            float mean = tot / fmaxf(cnt, 1.0f);
            if (cnt > 0.f) contrib = 0.1f * mean * w_b[bc];
        }
        #pragma unroll
        for (int o = 16; o; o >>= 1) contrib += __shfl_xor_sync(0xffffffffu, contrib, o);
        if (tid == 0) out[0] = contrib;
    }
    __syncthreads();

    // Re-zero accumulators for the next graph replay.
    if (tid < 32)          g_cls[tid]     = 0.f;
    if (tid < NCLS)        g_hist_t[tid]  = 0;
    if (tid < NCLS * NB)   g_hist_tb[tid] = 0;
}

// ---------------------------------------------------------------------------
extern "C" void kernel_launch(void* const* d_in, const int* in_sizes, int n_in,
                              void* d_out, int out_size) {
    const float* x       = (const float*)d_in[0];
    const float* temp    = (const float*)d_in[1];
    const float* w_t     = (const float*)d_in[2];
    const float* w_b     = (const float*)d_in[3];
    const int*   targets = (const int*)d_in[4];
    const int*   batch0  = (const int*)d_in[5];
    float*       out     = (float*)d_out;

    k_prep<<<NORMB, 256>>>(x, targets, batch0);

    cudaFuncSetAttribute(k_main, cudaFuncAttributeMaxDynamicSharedMemorySize, SMEM_TOTAL);
    k_main<<<NPAIRS, 256, SMEM_TOTAL>>>(temp, targets, batch0);

    k_tail<<<NN / 256, 256>>>(targets, batch0);
    k_fin<<<1, 128>>>(w_t, w_b, out);
}

// round 17
// speedup vs baseline: 1.3338x; 1.3338x over previous
#include <cuda_runtime.h>
#include <cuda_fp16.h>
#include <math.h>
#include <stdint.h>

// Problem constants
#define NN    6144
#define DD    128
#define NCLS  20
#define NB    5

#define ITILES 48                     // 6144/128
#define NPAIRS (ITILES*(ITILES+1)/2)  // 1176 tile pairs (I<=J)
#define JSPLIT ITILES

#define TBLK  768                     // k_tail blocks (8 rows each)
#define NORMB 384                     // norm blocks inside k_prep

// SMEM layout for k_main. Tile rows = 256B (128 fp16), 16B-chunk XOR swizzle.
#define OFF_A    0
#define OFF_B    32768
#define OFF_KI   65536
#define OFF_KJ   (OFF_KI + 512)
#define OFF_RED1 OFF_A               // aliased onto dead A tile
#define OFF_RED2 (OFF_A + 8192)
#define SMEM_TOTAL (OFF_KJ + 512)    // ~65.5KB -> 2 CTA/SM

__device__ __forceinline__ uint32_t smem_u32(const void* p) {
    uint32_t a;
    asm("{ .reg .u64 t; cvta.to.shared.u64 t, %1; cvt.u32.u64 %0, t; }" : "=r"(a) : "l"(p));
    return a;
}

#define LDSM_X4(r0, r1, r2, r3, addr) \
    asm volatile("ldmatrix.sync.aligned.m8n8.x4.shared.b16 {%0,%1,%2,%3}, [%4];" \
                 : "=r"(r0), "=r"(r1), "=r"(r2), "=r"(r3) : "r"(addr))

#define MMA_F16(c, a, b0, b1) \
    asm volatile("mma.sync.aligned.m16n8k16.row.col.f32.f16.f16.f32 " \
                 "{%0,%1,%2,%3}, {%4,%5,%6,%7}, {%8,%9}, {%0,%1,%2,%3};" \
                 : "+f"((c)[0]), "+f"((c)[1]), "+f"((c)[2]), "+f"((c)[3]) \
                 : "r"((a)[0]), "r"((a)[1]), "r"((a)[2]), "r"((a)[3]), "r"(b0), "r"(b1))

// ---------------- Scratch (device globals; zero-initialized at load) -------
__device__ __half g_h[NN * DD];
__device__ float g_part[NN * JSPLIT * 4];   // [row][split][4]
__device__ int   g_hist_t[NCLS];
__device__ int   g_hist_tb[NCLS * NB];
__device__ float g_cls[32];                 // class sums; zeroed at load, re-zeroed by last block
__device__ unsigned int g_done;             // reset by k_prep each call

// ---------------------------------------------------------------------------
// Kernel 1: prep = normalize+fp16 (blocks 0..383) + histogram & resets
// (block 384).   [R13 structure]
// ---------------------------------------------------------------------------
__global__ void k_prep(const float* __restrict__ x,
                       const int* __restrict__ targets,
                       const int* __restrict__ batch0) {
    if (blockIdx.x < NORMB) {
        int row0 = blockIdx.x * 16 + (threadIdx.x >> 5) * 2;
        int lane = threadIdx.x & 31;
        float4 v0 = *(const float4*)(x + (size_t)row0 * DD + lane * 4);
        float4 v1 = *(const float4*)(x + (size_t)(row0 + 1) * DD + lane * 4);
        float s0 = v0.x * v0.x + v0.y * v0.y + v0.z * v0.z + v0.w * v0.w;
        float s1 = v1.x * v1.x + v1.y * v1.y + v1.z * v1.z + v1.w * v1.w;
        #pragma unroll
        for (int o = 16; o; o >>= 1) {
            s0 += __shfl_xor_sync(0xffffffffu, s0, o);
            s1 += __shfl_xor_sync(0xffffffffu, s1, o);
        }
        float i0 = 1.0f / fmaxf(sqrtf(s0), 1e-8f);
        float i1 = 1.0f / fmaxf(sqrtf(s1), 1e-8f);
        size_t b0 = (size_t)row0 * DD + lane * 4;
        *(__half2*)(g_h + b0)          = __floats2half2_rn(v0.x * i0, v0.y * i0);
        *(__half2*)(g_h + b0 + 2)      = __floats2half2_rn(v0.z * i0, v0.w * i0);
        *(__half2*)(g_h + b0 + DD)     = __floats2half2_rn(v1.x * i1, v1.y * i1);
        *(__half2*)(g_h + b0 + DD + 2) = __floats2half2_rn(v1.z * i1, v1.w * i1);
    } else {
        __shared__ int ht[NCLS], htb[NCLS * NB];
        int tid = threadIdx.x;
        if (tid == 0) g_done = 0u;
        if (tid < NCLS)      ht[tid]  = 0;
        if (tid < NCLS * NB) htb[tid] = 0;
        __syncthreads();
        for (int i = tid; i < NN; i += blockDim.x) {
            int t = targets[i], b = batch0[i];
            atomicAdd(&ht[t], 1);
            atomicAdd(&htb[t * NB + b], 1);
        }
        __syncthreads();
        if (tid < NCLS)      g_hist_t[tid]  = ht[tid];
        if (tid < NCLS * NB) g_hist_tb[tid] = htb[tid];
    }
}

// ---------------------------------------------------------------------------
// Templated epilogue (DIAG: self-exclusion; FAST: t==0.25 -> et = eb*eb).
// ---------------------------------------------------------------------------
template <bool DIAG, bool FAST>
__device__ __forceinline__ void epilogue(
    const float (&acc)[4][4][4],
    const uint32_t (&kIa)[2], const uint32_t* kj8,
    float inv_t, float* red1, float* red2,
    int wm, int wn, int g, int q)
{
    float all2[8], st2[8], sb2[8], pb2[8];
    #pragma unroll
    for (int k = 0; k < 8; k++) { all2[k]=st2[k]=sb2[k]=pb2[k]=0.f; }

    #pragma unroll
    for (int mi = 0; mi < 4; mi++) {
        float a1[2] = {0.f, 0.f}, s1[2] = {0.f, 0.f};
        float b1[2] = {0.f, 0.f}, p1[2] = {0.f, 0.f};
        uint32_t kib[2];
        #pragma unroll
        for (int h = 0; h < 2; h++) {
            int pi = mi * 2 + h;
            kib[h] = (kIa[pi >> 2] >> ((pi & 3) * 8)) & 0xFFu;
        }

        #pragma unroll
        for (int ni = 0; ni < 4; ni++) {
            #pragma unroll
            for (int e = 0; e < 4; e++) {
                const int h  = e >> 1, l = e & 1;
                const int pj = ni * 2 + l;
                uint32_t x = kib[h] ^ kj8[pj];
                bool same_t = (x < 8u);
                bool eq     = (x == 0u);
                float s  = acc[mi][ni][e];
                float eb, et;
                if (FAST) { eb = __expf(s + s); et = eb * eb; }
                else      { eb = __expf(s + s); et = __expf(s * inv_t); }
                if (DIAG) {
                    bool self = ((wm * 64 + mi * 16 + h * 8 + g) ==
                                 (wn * 32 + ni * 8 + 2 * q + l));
                    et = self ? 0.f : et;
                    eb = self ? 0.f : eb;
                }
                float et_st = same_t ? et : 0.f;
                float eb_st = same_t ? eb : 0.f;
                float eb_eq = eq     ? eb : 0.f;
                a1[h] += et;    s1[h] += et_st;   b1[h] += eb_st;   p1[h] += eb_eq;
                all2[pj] += et; st2[pj] += et_st; sb2[pj] += eb_st; pb2[pj] += eb_eq;
            }
        }
        #pragma unroll
        for (int h = 0; h < 2; h++) {
            float pt = s1[h];
            float nt = a1[h] - s1[h];
            float pb = p1[h];
            float nb = b1[h] - p1[h];
            #pragma unroll
            for (int o = 1; o <= 2; o <<= 1) {
                pt += __shfl_xor_sync(0xffffffffu, pt, o);
                nt += __shfl_xor_sync(0xffffffffu, nt, o);
                pb += __shfl_xor_sync(0xffffffffu, pb, o);
                nb += __shfl_xor_sync(0xffffffffu, nb, o);
            }
            if (q == 0) {
                int row_loc = wm * 64 + mi * 16 + h * 8 + g;
                *(float4*)&red1[(wn * 128 + row_loc) * 4] = make_float4(pt, nt, pb, nb);
            }
        }
    }

    if (!DIAG) {
        #pragma unroll
        for (int k = 0; k < 8; k++) {
            float pt = st2[k];
            float nt = all2[k] - st2[k];
            float pb = pb2[k];
            float nb = sb2[k] - pb2[k];
            #pragma unroll
            for (int o = 4; o <= 16; o <<= 1) {
                pt += __shfl_xor_sync(0xffffffffu, pt, o);
                nt += __shfl_xor_sync(0xffffffffu, nt, o);
                pb += __shfl_xor_sync(0xffffffffu, pb, o);
                nb += __shfl_xor_sync(0xffffffffu, nb, o);
            }
            if (g == 0) {
                int row_loc = wn * 32 + (k >> 1) * 8 + 2 * q + (k & 1);
                *(float4*)&red2[(wm * 128 + row_loc) * 4] = make_float4(pt, nt, pb, nb);
            }
        }
    }
}

// ---------------------------------------------------------------------------
// Kernel 2: one CTA per tile pair (I,J), I<=J.   [R13 structure]
// ---------------------------------------------------------------------------
__device__ __forceinline__ void fill_tile(char* smem, int off,
                                          const __half* __restrict__ src,
                                          int rowbase, int tid) {
    #pragma unroll
    for (int it = 0; it < 8; it++) {
        int lin = it * 256 + tid;
        int n   = lin >> 4;
        int c16 = lin & 15;
        uint4 v = *(const uint4*)(src + (size_t)(rowbase + n) * DD + c16 * 8);
        *(uint4*)(smem + off + n * 256 + ((c16 ^ (n & 7)) << 4)) = v;
    }
}

__global__ void __launch_bounds__(256, 2)
k_main(const float* __restrict__ d_temp,
       const int*   __restrict__ targets,
       const int*   __restrict__ batch0) {
    extern __shared__ char smem[];
    const uint32_t sb = smem_u32(smem);
    const int tid = threadIdx.x;
    const int L   = tid & 31;
    const int w   = tid >> 5;
    const int wm  = w & 1;
    const int wn  = w >> 1;

    int p = blockIdx.x, I = 0;
    while (p >= ITILES - I) { p -= ITILES - I; I++; }
    const int J = I + p;
    const int Ibase = I * 128;
    const int Jbase = J * 128;
    const bool diag = (I == J);

    int*   sm_ki = (int*)(smem + OFF_KI);
    int*   sm_kj = (int*)(smem + OFF_KJ);
    float* red1  = (float*)(smem + OFF_RED1);
    float* red2  = (float*)(smem + OFF_RED2);

    const float t     = fminf(fmaxf(d_temp[0], 0.1f), 1.0f);
    const float inv_t = 1.0f / t;
    const bool  fast  = (inv_t == 4.0f);

    fill_tile(smem, OFF_A, g_h, Ibase, tid);
    fill_tile(smem, OFF_B, g_h, Jbase, tid);
    if (tid < 128) {
        sm_ki[tid] = targets[Ibase + tid] * 8 + batch0[Ibase + tid];
    } else {
        int r = tid - 128;
        sm_kj[r] = targets[Jbase + r] * 8 + batch0[Jbase + r];
    }
    __syncthreads();

    const int la15 = L & 15;
    const int l4   = L >> 4;
    const int lb7  = (L & 7) + ((L >> 4) << 3);
    const int lb1  = (L >> 3) & 1;

    float acc[4][4][4];
    #pragma unroll
    for (int mi = 0; mi < 4; mi++)
        #pragma unroll
        for (int ni = 0; ni < 4; ni++)
            #pragma unroll
            for (int e = 0; e < 4; e++) acc[mi][ni][e] = 0.f;

    #pragma unroll
    for (int ks = 0; ks < 8; ks++) {
        uint32_t a[4][4], b[2][4];
        #pragma unroll
        for (int mi = 0; mi < 4; mi++) {
            int rowA = wm * 64 + mi * 16 + la15;
            uint32_t ad = sb + OFF_A + rowA * 256 + (((ks * 2 + l4) ^ (rowA & 7)) << 4);
            LDSM_X4(a[mi][0], a[mi][1], a[mi][2], a[mi][3], ad);
        }
        #pragma unroll
        for (int np = 0; np < 2; np++) {
            int rowB = wn * 32 + np * 16 + lb7;
            uint32_t bd = sb + OFF_B + rowB * 256 + (((ks * 2 + lb1) ^ (rowB & 7)) << 4);
            LDSM_X4(b[np][0], b[np][1], b[np][2], b[np][3], bd);
        }
        #pragma unroll
        for (int mi = 0; mi < 4; mi++)
            #pragma unroll
            for (int ni = 0; ni < 4; ni++)
                MMA_F16(acc[mi][ni], a[mi],
                        b[ni >> 1][(ni & 1) * 2], b[ni >> 1][(ni & 1) * 2 + 1]);
    }

    const int g = L >> 2, q = L & 3;

    uint32_t kIa[2] = {0u, 0u};
    uint32_t kj8[8];
    #pragma unroll
    for (int pk = 0; pk < 8; pk++) {
        int row = wm * 64 + (pk >> 1) * 16 + (pk & 1) * 8 + g;
        kIa[pk >> 2] |= ((uint32_t)sm_ki[row]) << ((pk & 3) * 8);
        int col = wn * 32 + (pk >> 1) * 8 + 2 * q + (pk & 1);
        kj8[pk] = (uint32_t)sm_kj[col];
    }
    __syncthreads();

    if (diag) {
        if (fast) epilogue<true,  true >(acc, kIa, kj8, inv_t, red1, red2, wm, wn, g, q);
        else      epilogue<true,  false>(acc, kIa, kj8, inv_t, red1, red2, wm, wn, g, q);
    } else {
        if (fast) epilogue<false, true >(acc, kIa, kj8, inv_t, red1, red2, wm, wn, g, q);
        else      epilogue<false, false>(acc, kIa, kj8, inv_t, red1, red2, wm, wn, g, q);
    }
    __syncthreads();

    if (tid < 128) {
        float a = 0.f, b = 0.f, c = 0.f, d = 0.f;
        #pragma unroll
        for (int v = 0; v < 4; v++) {
            float4 r4 = *(const float4*)&red1[(v * 128 + tid) * 4];
            a += r4.x; b += r4.y; c += r4.z; d += r4.w;
        }
        *(float4*)(g_part + ((size_t)(Ibase + tid) * JSPLIT + J) * 4) = make_float4(a, b, c, d);
    } else if (!diag) {
        int r = tid - 128;
        float4 r0 = *(const float4*)&red2[(r) * 4];
        float4 r1 = *(const float4*)&red2[(128 + r) * 4];
        *(float4*)(g_part + ((size_t)(Jbase + r) * JSPLIT + I) * 4) =
            make_float4(r0.x + r1.x, r0.y + r1.y, r0.z + r1.z, r0.w + r1.w);
    }
}

// ---------------------------------------------------------------------------
// Kernel 3: tail (768 blocks, warp per row) + class float-atomics into g_cls
// + CHEAP last-block finale (reads 25 floats, writes out, re-zeros g_cls).
// ---------------------------------------------------------------------------
__global__ void k_tail(const int* __restrict__ targets,
                       const int* __restrict__ batch0,
                       const float* __restrict__ w_t,
                       const float* __restrict__ w_b,
                       float* __restrict__ out) {
    __shared__ float sm_lt[8], sm_lb[8];
    __shared__ int   sm_t[8],  sm_b[8];
    __shared__ bool  amLast;

    const int tid  = threadIdx.x;
    const int warp = tid >> 5;
    const int lane = tid & 31;
    const int i    = blockIdx.x * 8 + warp;

    const float* rowp = g_part + (size_t)i * (JSPLIT * 4);   // 192 floats
    float v = 0.f;
    #pragma unroll
    for (int m = 0; m < 6; m++) v += rowp[lane + m * 32];    // coalesced
    #pragma unroll
    for (int o = 4; o <= 16; o <<= 1) v += __shfl_xor_sync(0xffffffffu, v, o);

    float ptv = __shfl_sync(0xffffffffu, v, 0);
    float ntv = __shfl_sync(0xffffffffu, v, 1);
    float pbv = __shfl_sync(0xffffffffu, v, 2);
    float nbv = __shfl_sync(0xffffffffu, v, 3);

    if (lane == 0) {
        int tcl = targets[i], bcl = batch0[i];
        int cp  = g_hist_t[tcl];
        bool valid_t = (cp >= 2) && ((NN - cp) >= 1);
        int cpb = g_hist_tb[tcl * NB + bcl];
        int cnb = cp - cpb;
        bool valid_b = (cpb >= 2) && (cnb >= 1);
        sm_lt[warp] = valid_t ? logf((ptv + ntv) / ptv) : 0.0f;
        sm_lb[warp] = valid_b ? (1.0f / logf((pbv + nbv) / pbv)) : 0.0f;
        sm_t[warp]  = tcl;
        sm_b[warp]  = bcl;
    }
    __syncthreads();

    if (tid < NCLS + NB) {
        float s = 0.f;
        if (tid < NCLS) {
            #pragma unroll
            for (int k = 0; k < 8; k++)
                if (sm_t[k] == tid) s += sm_lt[k];
        } else {
            int bc = tid - NCLS;
            #pragma unroll
            for (int k = 0; k < 8; k++)
                if (sm_b[k] == bc) s += sm_lb[k];
        }
        if (s != 0.f) atomicAdd(&g_cls[tid], s);
    }

    // ---- last-block finale (reads 25 floats only) ----
    __threadfence();
    __syncthreads();
    if (tid == 0) {
        unsigned int prev = atomicAdd(&g_done, 1u);
        amLast = (prev == (unsigned int)(TBLK - 1));
    }
    __syncthreads();
    if (!amLast) return;
    __threadfence();

    if (tid < 32) {
        float tot = (tid < NCLS + NB) ? g_cls[tid] : 0.f;
        float contrib = 0.f;
        if (tid < NCLS) {
            int cp = g_hist_t[tid];
            bool valid = (cp >= 2) && ((NN - cp) >= 1);
            float cnt = valid ? (float)cp : 0.f;
            float mean = tot / fmaxf(cnt, 1.0f);
            if (cnt > 0.f) contrib = 0.9f * mean * w_t[tid];
        } else if (tid < NCLS + NB) {
            int bc = tid - NCLS;
            float cnt = 0.f;
            for (int tc = 0; tc < NCLS; tc++) {
                int cpb = g_hist_tb[tc * NB + bc];
                int cnb = g_hist_t[tc] - cpb;
                if ((cpb >= 2) && (cnb >= 1)) cnt += (float)cpb;
            }
            float mean = tot / fmaxf(cnt, 1.0f);
            if (cnt > 0.f) contrib = 0.1f * mean * w_b[bc];
        }
        #pragma unroll
        for (int o = 16; o; o >>= 1) contrib += __shfl_xor_sync(0xffffffffu, contrib, o);
        if (tid == 0) out[0] = contrib;
        // re-zero class sums for the next graph replay
        g_cls[tid] = 0.f;
    }
}

// ---------------------------------------------------------------------------
extern "C" void kernel_launch(void* const* d_in, const int* in_sizes, int n_in,
                              void* d_out, int out_size) {
    const float* x       = (const float*)d_in[0];
    const float* temp    = (const float*)d_in[1];
    const float* w_t     = (const float*)d_in[2];
    const float* w_b     = (const float*)d_in[3];
    const int*   targets = (const int*)d_in[4];
    const int*   batch0  = (const int*)d_in[5];
    float*       out     = (float*)d_out;

    k_prep<<<NORMB + 1, 256>>>(x, targets, batch0);

    cudaFuncSetAttribute(k_main, cudaFuncAttributeMaxDynamicSharedMemorySize, SMEM_TOTAL);
    k_main<<<NPAIRS, 256, SMEM_TOTAL>>>(temp, targets, batch0);

    k_tail<<<TBLK, 256>>>(targets, batch0, w_t, w_b, out);
}